// round 2
// baseline (speedup 1.0000x reference)
#include <cuda_runtime.h>
#include <cuda_bf16.h>
#include <math.h>

#define H_DIM 768
#define T_TAGS 3
#define S_LEN 512
#define B_SZ 128
#define ROWS_PER_WARP 8
#define F4_PER_ROW (H_DIM / 4)      // 192
#define F4_PER_LANE (H_DIM / 128)   // 6

// -------------------- kernel 1: prediction = inputs @ W^T + b --------------------
// Warp-per-row, software-pipelined: row r+1's 6 LDG.128 are issued while row r's
// FMAs run, keeping ~6 independent global loads in flight per warp at all times.
__global__ __launch_bounds__(256) void pred_kernel(
    const float* __restrict__ x, const float* __restrict__ W,
    const float* __restrict__ bias, float* __restrict__ out, int nrows)
{
    __shared__ float4 ws[3 * F4_PER_ROW];   // 9 KB
    __shared__ float bs[3];
    for (int i = threadIdx.x; i < 3 * F4_PER_ROW; i += blockDim.x)
        ws[i] = reinterpret_cast<const float4*>(W)[i];
    if (threadIdx.x < 3) bs[threadIdx.x] = bias[threadIdx.x];
    __syncthreads();

    int gw   = (blockIdx.x * blockDim.x + threadIdx.x) >> 5;
    int lane = threadIdx.x & 31;
    int row0 = gw * ROWS_PER_WARP;
    if (row0 >= nrows) return;

    const float4* xr = reinterpret_cast<const float4*>(x)
                       + (size_t)row0 * F4_PER_ROW + lane;

    // Preload W slices this lane will reuse for every row (stay in regs).
    float4 w0[F4_PER_LANE], w1[F4_PER_LANE], w2[F4_PER_LANE];
    #pragma unroll
    for (int i = 0; i < F4_PER_LANE; i++) {
        w0[i] = ws[i * 32 + lane];
        w1[i] = ws[192 + i * 32 + lane];
        w2[i] = ws[384 + i * 32 + lane];
    }

    // Prologue: load row 0.
    float4 v[F4_PER_LANE];
    #pragma unroll
    for (int i = 0; i < F4_PER_LANE; i++)
        v[i] = __ldcs(&xr[i * 32]);

    #pragma unroll
    for (int r = 0; r < ROWS_PER_WARP; r++) {
        // Prefetch next row while computing this one.
        float4 vn[F4_PER_LANE];
        if (r + 1 < ROWS_PER_WARP) {
            const float4* xn = xr + (size_t)(r + 1) * F4_PER_ROW;
            #pragma unroll
            for (int i = 0; i < F4_PER_LANE; i++)
                vn[i] = __ldcs(&xn[i * 32]);
        }

        float a0 = 0.f, a1 = 0.f, a2 = 0.f;
        #pragma unroll
        for (int i = 0; i < F4_PER_LANE; i++) {
            float4 t = v[i];
            a0 = fmaf(t.x, w0[i].x, fmaf(t.y, w0[i].y, fmaf(t.z, w0[i].z, fmaf(t.w, w0[i].w, a0))));
            a1 = fmaf(t.x, w1[i].x, fmaf(t.y, w1[i].y, fmaf(t.z, w1[i].z, fmaf(t.w, w1[i].w, a1))));
            a2 = fmaf(t.x, w2[i].x, fmaf(t.y, w2[i].y, fmaf(t.z, w2[i].z, fmaf(t.w, w2[i].w, a2))));
        }
        #pragma unroll
        for (int off = 16; off; off >>= 1) {
            a0 += __shfl_xor_sync(0xffffffffu, a0, off);
            a1 += __shfl_xor_sync(0xffffffffu, a1, off);
            a2 += __shfl_xor_sync(0xffffffffu, a2, off);
        }
        if (lane == 0) {
            float* o = out + (size_t)(row0 + r) * 3;
            o[0] = a0 + bs[0];
            o[1] = a1 + bs[1];
            o[2] = a2 + bs[2];
        }
        #pragma unroll
        for (int i = 0; i < F4_PER_LANE; i++) v[i] = vn[i];
    }
}

// -------------------- CRF pieces --------------------
__device__ float g_part[B_SZ];

// Fast log-sum-exp of 3 (MUFU EX2/LG2; rel err ~2^-21, far below 1e-3 tol).
__device__ __forceinline__ float lse3(float x, float y, float z) {
    float m = fmaxf(x, fmaxf(y, z));
    return m + __logf(__expf(x - m) + __expf(y - m) + __expf(z - m));
}

// One block per batch element. Tree-reduce 512 3x3 log-semiring matrices.
__global__ __launch_bounds__(256) void crf_kernel(
    const float* __restrict__ pred, const void* __restrict__ yraw,
    const float* __restrict__ trans, const float* __restrict__ start_t,
    const float* __restrict__ stop_t)
{
    __shared__ float feats[S_LEN * 3];      // 6 KB
    __shared__ float mats[S_LEN * 9];       // 18 KB
    __shared__ float buf[256 * 9];          // 9 KB
    __shared__ float red[256];
    __shared__ float tr[9], st[3], sp[3];
    __shared__ int is64_s;

    int b   = blockIdx.x;
    int tid = threadIdx.x;

    if (tid < 9) tr[tid] = trans[tid];
    if (tid < 3) { st[tid] = start_t[tid]; sp[tid] = stop_t[tid]; }

    // Detect whether y is int64 or int32 (values 0..2; little-endian int64 ->
    // every odd 32-bit word zero; false-positive prob ~3^-16).
    if (tid == 0) {
        const int* y32p = (const int*)yraw;
        int is64 = 1;
        #pragma unroll
        for (int k = 0; k < 16; k++)
            if (y32p[2 * k + 1] != 0) { is64 = 0; break; }
        is64_s = is64;
    }

    const float* pb = pred + (size_t)b * S_LEN * 3;
    for (int i = tid; i < S_LEN * 3; i += 256) feats[i] = pb[i];
    __syncthreads();

    const int is64 = is64_s;
    const long long* y64 = (const long long*)yraw + (size_t)b * S_LEN;
    const int*       y32 = (const int*)yraw       + (size_t)b * S_LEN;
    #define TAG(s) (is64 ? (int)y64[(s)] : y32[(s)])

    // ---- gold path score ----
    float acc = 0.f;
    for (int s = tid; s < S_LEN; s += 256) {
        int tg = TAG(s);
        acc += feats[s * 3 + tg];
        if (s > 0) { int tp = TAG(s - 1); acc += tr[tp * 3 + tg]; }
    }
    if (tid == 0) acc += st[TAG(0)] + sp[TAG(S_LEN - 1)];
    red[tid] = acc;
    __syncthreads();
    for (int h = 128; h; h >>= 1) {
        if (tid < h) red[tid] += red[tid + h];
        __syncthreads();
    }
    float seq_score = red[0];

    // ---- build 512 log-semiring matrices ----
    // M_0[i][j] = feats[0][j] + start[j] (rank-1); M_t[i][j] = trans[i][j] + feats[t][j]
    for (int i = tid; i < S_LEN * 9; i += 256) {
        int t = i / 9, e = i % 9, col = e % 3;
        mats[i] = (t == 0) ? (feats[col] + st[col]) : (tr[e] + feats[t * 3 + col]);
    }
    __syncthreads();

    // ---- tree reduction (order-preserving pairwise product) ----
    float* src = mats;
    float* dst = buf;
    int n = S_LEN;
    while (n > 1) {
        int half = n >> 1;
        if (tid < half) {
            const float* A  = src + (size_t)(2 * tid) * 9;
            const float* Bm = src + (size_t)(2 * tid + 1) * 9;
            float c[9];
            #pragma unroll
            for (int i2 = 0; i2 < 3; i2++)
                #pragma unroll
                for (int j = 0; j < 3; j++)
                    c[i2 * 3 + j] = lse3(A[i2 * 3 + 0] + Bm[0 * 3 + j],
                                         A[i2 * 3 + 1] + Bm[1 * 3 + j],
                                         A[i2 * 3 + 2] + Bm[2 * 3 + j]);
            #pragma unroll
            for (int e = 0; e < 9; e++) dst[tid * 9 + e] = c[e];
        }
        __syncthreads();
        float* tmp = src; src = dst; dst = tmp;
        n = half;
    }

    if (tid == 0) {
        float logz = lse3(src[0] + sp[0], src[1] + sp[1], src[2] + sp[2]);
        g_part[b] = seq_score - logz;
    }
    #undef TAG
}

// -------------------- kernel 3: mean-reduce 128 partials --------------------
__global__ void finalize_kernel(float* loss_out) {
    __shared__ float red[B_SZ];
    int tid = threadIdx.x;
    red[tid] = g_part[tid];
    __syncthreads();
    for (int h = B_SZ / 2; h; h >>= 1) {
        if (tid < h) red[tid] += red[tid + h];
        __syncthreads();
    }
    if (tid == 0) *loss_out = -red[0] / (float)B_SZ;
}

// -------------------- launch --------------------
extern "C" void kernel_launch(void* const* d_in, const int* in_sizes, int n_in,
                              void* d_out, int out_size)
{
    const float* x     = (const float*)d_in[0];
    const void*  y     = d_in[1];
    const float* W     = (const float*)d_in[2];
    const float* bias  = (const float*)d_in[3];
    const float* trans = (const float*)d_in[4];
    const float* st    = (const float*)d_in[5];
    const float* sp    = (const float*)d_in[6];
    float* out = (float*)d_out;

    int nrows = in_sizes[0] / H_DIM;                       // 65536
    int warps = (nrows + ROWS_PER_WARP - 1) / ROWS_PER_WARP;
    int blocks = (warps * 32 + 255) / 256;

    pred_kernel<<<blocks, 256>>>(x, W, bias, out, nrows);
    crf_kernel<<<B_SZ, 256>>>(out, y, trans, st, sp);
    finalize_kernel<<<1, B_SZ>>>(out + (out_size - 1));
}

// round 3
// speedup vs baseline: 1.2938x; 1.2938x over previous
#include <cuda_runtime.h>
#include <cuda_bf16.h>
#include <math.h>

#define H_DIM 768
#define T_TAGS 3
#define S_LEN 512
#define B_SZ 128
#define F4_PER_ROW (H_DIM / 4)      // 192
#define CHUNKS (H_DIM / 128)        // 6 h-chunks of 32 float4
#define RQ 4                        // rows per quad
#define QUADS_PER_WARP 2            // 8 rows per warp total

// -------------------- kernel 1: prediction = inputs @ W^T + b --------------------
// 4 rows per warp-iteration: W shared-loads amortized 4x (L1 wavefronts/row 96->42).
__global__ __launch_bounds__(256) void pred_kernel(
    const float* __restrict__ x, const float* __restrict__ W,
    const float* __restrict__ bias, float* __restrict__ out, int nrows)
{
    __shared__ float4 ws[3 * F4_PER_ROW];   // 9 KB
    __shared__ float bs[3];
    for (int i = threadIdx.x; i < 3 * F4_PER_ROW; i += blockDim.x)
        ws[i] = reinterpret_cast<const float4*>(W)[i];
    if (threadIdx.x < 3) bs[threadIdx.x] = bias[threadIdx.x];
    __syncthreads();

    int gw   = (blockIdx.x * blockDim.x + threadIdx.x) >> 5;
    int lane = threadIdx.x & 31;
    int wrow0 = gw * (RQ * QUADS_PER_WARP);
    if (wrow0 >= nrows) return;

    #pragma unroll
    for (int qd = 0; qd < QUADS_PER_WARP; qd++) {
        int row0 = wrow0 + qd * RQ;
        const float4* xr = reinterpret_cast<const float4*>(x)
                           + (size_t)row0 * F4_PER_ROW + lane;

        float a[RQ][3];
        #pragma unroll
        for (int q = 0; q < RQ; q++) { a[q][0] = 0.f; a[q][1] = 0.f; a[q][2] = 0.f; }

        #pragma unroll
        for (int i = 0; i < CHUNKS; i++) {
            // 4 independent x loads + 3 W loads per chunk (all independent -> MLP)
            float4 xv[RQ];
            #pragma unroll
            for (int q = 0; q < RQ; q++)
                xv[q] = __ldcs(&xr[(size_t)q * F4_PER_ROW + i * 32]);
            float4 w0 = ws[i * 32 + lane];
            float4 w1 = ws[192 + i * 32 + lane];
            float4 w2 = ws[384 + i * 32 + lane];
            #pragma unroll
            for (int q = 0; q < RQ; q++) {
                float4 t = xv[q];
                a[q][0] = fmaf(t.x, w0.x, fmaf(t.y, w0.y, fmaf(t.z, w0.z, fmaf(t.w, w0.w, a[q][0]))));
                a[q][1] = fmaf(t.x, w1.x, fmaf(t.y, w1.y, fmaf(t.z, w1.z, fmaf(t.w, w1.w, a[q][1]))));
                a[q][2] = fmaf(t.x, w2.x, fmaf(t.y, w2.y, fmaf(t.z, w2.z, fmaf(t.w, w2.w, a[q][2]))));
            }
        }

        // Butterfly reduce all 12 sums (every lane ends with totals),
        // then lanes 0..3 each store one row.
        #pragma unroll
        for (int off = 16; off; off >>= 1) {
            #pragma unroll
            for (int q = 0; q < RQ; q++) {
                a[q][0] += __shfl_xor_sync(0xffffffffu, a[q][0], off);
                a[q][1] += __shfl_xor_sync(0xffffffffu, a[q][1], off);
                a[q][2] += __shfl_xor_sync(0xffffffffu, a[q][2], off);
            }
        }
        if (lane < RQ) {
            float* o = out + (size_t)(row0 + lane) * 3;
            o[0] = a[lane][0] + bs[0];
            o[1] = a[lane][1] + bs[1];
            o[2] = a[lane][2] + bs[2];
        }
    }
}

// -------------------- CRF pieces --------------------
__device__ float g_part[B_SZ];

// Fast log-sum-exp of 3 (MUFU EX2/LG2; rel err ~2^-21, far below 1e-3 tol).
__device__ __forceinline__ float lse3(float x, float y, float z) {
    float m = fmaxf(x, fmaxf(y, z));
    return m + __logf(__expf(x - m) + __expf(y - m) + __expf(z - m));
}

// One block per batch element. Tree-reduce 512 3x3 log-semiring matrices.
__global__ __launch_bounds__(256) void crf_kernel(
    const float* __restrict__ pred, const void* __restrict__ yraw,
    const float* __restrict__ trans, const float* __restrict__ start_t,
    const float* __restrict__ stop_t)
{
    __shared__ float feats[S_LEN * 3];      // 6 KB
    __shared__ float mats[S_LEN * 9];       // 18 KB
    __shared__ float buf[256 * 9];          // 9 KB
    __shared__ float red[256];
    __shared__ float tr[9], st[3], sp[3];
    __shared__ int is64_s;

    int b   = blockIdx.x;
    int tid = threadIdx.x;

    if (tid < 9) tr[tid] = trans[tid];
    if (tid < 3) { st[tid] = start_t[tid]; sp[tid] = stop_t[tid]; }

    // Detect whether y is int64 or int32 (values 0..2; little-endian int64 ->
    // every odd 32-bit word zero; false-positive prob ~3^-16).
    if (tid == 0) {
        const int* y32p = (const int*)yraw;
        int is64 = 1;
        #pragma unroll
        for (int k = 0; k < 16; k++)
            if (y32p[2 * k + 1] != 0) { is64 = 0; break; }
        is64_s = is64;
    }

    const float* pb = pred + (size_t)b * S_LEN * 3;
    for (int i = tid; i < S_LEN * 3; i += 256) feats[i] = pb[i];
    __syncthreads();

    const int is64 = is64_s;
    const long long* y64 = (const long long*)yraw + (size_t)b * S_LEN;
    const int*       y32 = (const int*)yraw       + (size_t)b * S_LEN;
    #define TAG(s) (is64 ? (int)y64[(s)] : y32[(s)])

    // ---- gold path score ----
    float acc = 0.f;
    for (int s = tid; s < S_LEN; s += 256) {
        int tg = TAG(s);
        acc += feats[s * 3 + tg];
        if (s > 0) { int tp = TAG(s - 1); acc += tr[tp * 3 + tg]; }
    }
    if (tid == 0) acc += st[TAG(0)] + sp[TAG(S_LEN - 1)];
    red[tid] = acc;
    __syncthreads();
    for (int h = 128; h; h >>= 1) {
        if (tid < h) red[tid] += red[tid + h];
        __syncthreads();
    }
    float seq_score = red[0];

    // ---- build 512 log-semiring matrices ----
    // M_0[i][j] = feats[0][j] + start[j] (rank-1); M_t[i][j] = trans[i][j] + feats[t][j]
    for (int i = tid; i < S_LEN * 9; i += 256) {
        int t = i / 9, e = i % 9, col = e % 3;
        mats[i] = (t == 0) ? (feats[col] + st[col]) : (tr[e] + feats[t * 3 + col]);
    }
    __syncthreads();

    // ---- tree reduction (order-preserving pairwise product) ----
    float* src = mats;
    float* dst = buf;
    int n = S_LEN;
    while (n > 1) {
        int half = n >> 1;
        if (tid < half) {
            const float* A  = src + (size_t)(2 * tid) * 9;
            const float* Bm = src + (size_t)(2 * tid + 1) * 9;
            float c[9];
            #pragma unroll
            for (int i2 = 0; i2 < 3; i2++)
                #pragma unroll
                for (int j = 0; j < 3; j++)
                    c[i2 * 3 + j] = lse3(A[i2 * 3 + 0] + Bm[0 * 3 + j],
                                         A[i2 * 3 + 1] + Bm[1 * 3 + j],
                                         A[i2 * 3 + 2] + Bm[2 * 3 + j]);
            #pragma unroll
            for (int e = 0; e < 9; e++) dst[tid * 9 + e] = c[e];
        }
        __syncthreads();
        float* tmp = src; src = dst; dst = tmp;
        n = half;
    }

    if (tid == 0) {
        float logz = lse3(src[0] + sp[0], src[1] + sp[1], src[2] + sp[2]);
        g_part[b] = seq_score - logz;
    }
    #undef TAG
}

// -------------------- kernel 3: mean-reduce 128 partials --------------------
__global__ void finalize_kernel(float* loss_out) {
    __shared__ float red[B_SZ];
    int tid = threadIdx.x;
    red[tid] = g_part[tid];
    __syncthreads();
    for (int h = B_SZ / 2; h; h >>= 1) {
        if (tid < h) red[tid] += red[tid + h];
        __syncthreads();
    }
    if (tid == 0) *loss_out = -red[0] / (float)B_SZ;
}

// -------------------- launch --------------------
extern "C" void kernel_launch(void* const* d_in, const int* in_sizes, int n_in,
                              void* d_out, int out_size)
{
    const float* x     = (const float*)d_in[0];
    const void*  y     = d_in[1];
    const float* W     = (const float*)d_in[2];
    const float* bias  = (const float*)d_in[3];
    const float* trans = (const float*)d_in[4];
    const float* st    = (const float*)d_in[5];
    const float* sp    = (const float*)d_in[6];
    float* out = (float*)d_out;

    int nrows = in_sizes[0] / H_DIM;                       // 65536
    int rows_per_warp = RQ * QUADS_PER_WARP;               // 8
    int warps = (nrows + rows_per_warp - 1) / rows_per_warp;
    int blocks = (warps * 32 + 255) / 256;                 // 1024

    pred_kernel<<<blocks, 256>>>(x, W, bias, out, nrows);
    crf_kernel<<<B_SZ, 256>>>(out, y, trans, st, sp);
    finalize_kernel<<<1, B_SZ>>>(out + (out_size - 1));
}

// round 4
// speedup vs baseline: 1.4111x; 1.0907x over previous
#include <cuda_runtime.h>
#include <cuda_bf16.h>
#include <math.h>

#define H_DIM 768
#define T_TAGS 3
#define S_LEN 512
#define B_SZ 128
#define F4_PER_ROW (H_DIM / 4)      // 192
#define CHUNKS (H_DIM / 128)        // 6 h-chunks of 32 float4
#define RQ 4                        // rows per quad
#define QUADS_PER_WARP 2            // 8 rows per warp total
#define LN2F 0.6931471805599453f

// -------------------- kernel 1: prediction = inputs @ W^T + b --------------------
// 4 rows per warp-iteration, W amortized; min-4-blocks bound caps regs at 64
// so 4 blocks/SM fit -> occ ~50% -> more loads in flight.
__global__ __launch_bounds__(256, 4) void pred_kernel(
    const float* __restrict__ x, const float* __restrict__ W,
    const float* __restrict__ bias, float* __restrict__ out, int nrows)
{
    __shared__ float4 ws[3 * F4_PER_ROW];   // 9 KB
    __shared__ float bs[3];
    for (int i = threadIdx.x; i < 3 * F4_PER_ROW; i += blockDim.x)
        ws[i] = reinterpret_cast<const float4*>(W)[i];
    if (threadIdx.x < 3) bs[threadIdx.x] = bias[threadIdx.x];
    __syncthreads();

    int gw   = (blockIdx.x * blockDim.x + threadIdx.x) >> 5;
    int lane = threadIdx.x & 31;
    int wrow0 = gw * (RQ * QUADS_PER_WARP);
    if (wrow0 >= nrows) return;

    #pragma unroll
    for (int qd = 0; qd < QUADS_PER_WARP; qd++) {
        int row0 = wrow0 + qd * RQ;
        const float4* xr = reinterpret_cast<const float4*>(x)
                           + (size_t)row0 * F4_PER_ROW + lane;

        float a[RQ][3];
        #pragma unroll
        for (int q = 0; q < RQ; q++) { a[q][0] = 0.f; a[q][1] = 0.f; a[q][2] = 0.f; }

        #pragma unroll
        for (int i = 0; i < CHUNKS; i++) {
            float4 xv[RQ];
            #pragma unroll
            for (int q = 0; q < RQ; q++)
                xv[q] = __ldcs(&xr[(size_t)q * F4_PER_ROW + i * 32]);
            float4 w0 = ws[i * 32 + lane];
            float4 w1 = ws[192 + i * 32 + lane];
            float4 w2 = ws[384 + i * 32 + lane];
            #pragma unroll
            for (int q = 0; q < RQ; q++) {
                float4 t = xv[q];
                a[q][0] = fmaf(t.x, w0.x, fmaf(t.y, w0.y, fmaf(t.z, w0.z, fmaf(t.w, w0.w, a[q][0]))));
                a[q][1] = fmaf(t.x, w1.x, fmaf(t.y, w1.y, fmaf(t.z, w1.z, fmaf(t.w, w1.w, a[q][1]))));
                a[q][2] = fmaf(t.x, w2.x, fmaf(t.y, w2.y, fmaf(t.z, w2.z, fmaf(t.w, w2.w, a[q][2]))));
            }
        }

        #pragma unroll
        for (int off = 16; off; off >>= 1) {
            #pragma unroll
            for (int q = 0; q < RQ; q++) {
                a[q][0] += __shfl_xor_sync(0xffffffffu, a[q][0], off);
                a[q][1] += __shfl_xor_sync(0xffffffffu, a[q][1], off);
                a[q][2] += __shfl_xor_sync(0xffffffffu, a[q][2], off);
            }
        }
        if (lane < RQ) {
            float* o = out + (size_t)(row0 + lane) * 3;
            o[0] = a[lane][0] + bs[0];
            o[1] = a[lane][1] + bs[1];
            o[2] = a[lane][2] + bs[2];
        }
    }
}

// -------------------- CRF --------------------
__device__ float g_part[B_SZ];

// Linear-domain CRF: leaves are exp(M_t) = exp(trans) (x) exp(feats_t) (rank-1
// separable: 3 EX2 per leaf). Tree products are plain 3x3 fp32 matmuls with
// power-of-2 renormalization via exponent-bit extraction (zero MUFU in tree).
__global__ __launch_bounds__(256) void crf_kernel(
    const float* __restrict__ pred, const void* __restrict__ yraw,
    const float* __restrict__ trans, const float* __restrict__ start_t,
    const float* __restrict__ stop_t)
{
    __shared__ float feats[S_LEN * 3];      // 6 KB
    __shared__ float mats[S_LEN * 9];       // 18 KB
    __shared__ float buf[256 * 9];          // 9 KB
    __shared__ float lsA[S_LEN];            // 2 KB  per-node log-scale
    __shared__ float lsB[256];              // 1 KB
    __shared__ float red[256];
    __shared__ float tr[9], etr[9], st[3], sp[3];
    __shared__ int is64_s;

    int b   = blockIdx.x;
    int tid = threadIdx.x;

    if (tid < 9) { float t = trans[tid]; tr[tid] = t; etr[tid] = __expf(t); }
    if (tid < 3) { st[tid] = start_t[tid]; sp[tid] = stop_t[tid]; }

    // y dtype sniff (values 0..2; LE int64 -> odd words zero; FP prob ~3^-16)
    if (tid == 0) {
        const int* y32p = (const int*)yraw;
        int is64 = 1;
        #pragma unroll
        for (int k = 0; k < 16; k++)
            if (y32p[2 * k + 1] != 0) { is64 = 0; break; }
        is64_s = is64;
    }

    const float* pb = pred + (size_t)b * S_LEN * 3;
    for (int i = tid; i < S_LEN * 3; i += 256) feats[i] = pb[i];
    __syncthreads();

    const int is64 = is64_s;
    const long long* y64 = (const long long*)yraw + (size_t)b * S_LEN;
    const int*       y32 = (const int*)yraw       + (size_t)b * S_LEN;
    #define TAG(s) (is64 ? (int)y64[(s)] : y32[(s)])

    // ---- gold path score ----
    float acc = 0.f;
    for (int s = tid; s < S_LEN; s += 256) {
        int tg = TAG(s);
        acc += feats[s * 3 + tg];
        if (s > 0) { int tp = TAG(s - 1); acc += tr[tp * 3 + tg]; }
    }
    if (tid == 0) acc += st[TAG(0)] + sp[TAG(S_LEN - 1)];
    red[tid] = acc;
    __syncthreads();
    for (int h = 128; h; h >>= 1) {
        if (tid < h) red[tid] += red[tid + h];
        __syncthreads();
    }
    float seq_score = red[0];

    // ---- build 512 linear-domain leaf matrices ----
    for (int t = tid; t < S_LEN; t += 256) {
        float f0, f1, f2;
        if (t == 0) { f0 = feats[0] + st[0]; f1 = feats[1] + st[1]; f2 = feats[2] + st[2]; }
        else        { f0 = feats[t*3]; f1 = feats[t*3+1]; f2 = feats[t*3+2]; }
        float c = fmaxf(f0, fmaxf(f1, f2));
        float e0 = __expf(f0 - c), e1 = __expf(f1 - c), e2 = __expf(f2 - c);
        float* m = mats + t * 9;
        if (t == 0) {
            // rank-1 leaf: all rows = ef
            m[0]=e0; m[1]=e1; m[2]=e2; m[3]=e0; m[4]=e1; m[5]=e2; m[6]=e0; m[7]=e1; m[8]=e2;
        } else {
            m[0]=etr[0]*e0; m[1]=etr[1]*e1; m[2]=etr[2]*e2;
            m[3]=etr[3]*e0; m[4]=etr[4]*e1; m[5]=etr[5]*e2;
            m[6]=etr[6]*e0; m[7]=etr[7]*e1; m[8]=etr[8]*e2;
        }
        lsA[t] = c;
    }
    __syncthreads();

    // ---- tree reduction: numeric 3x3 matmuls + pow2 renorm (no MUFU) ----
    float* src = mats;  float* dst = buf;
    float* lss = lsA;   float* lsd = lsB;
    int n = S_LEN;
    while (n > 1) {
        int half = n >> 1;
        if (tid < half) {
            const float* A  = src + (size_t)(2 * tid) * 9;
            const float* Bm = src + (size_t)(2 * tid + 1) * 9;
            float c[9];
            #pragma unroll
            for (int i2 = 0; i2 < 3; i2++)
                #pragma unroll
                for (int j = 0; j < 3; j++)
                    c[i2 * 3 + j] = fmaf(A[i2*3+0], Bm[0*3+j],
                                    fmaf(A[i2*3+1], Bm[1*3+j],
                                         A[i2*3+2] * Bm[2*3+j]));
            float m = c[0];
            #pragma unroll
            for (int e = 1; e < 9; e++) m = fmaxf(m, c[e]);
            // power-of-2 renormalization: s = 2^-e exactly, ls += e*ln2
            int ebits = (__float_as_int(m) >> 23) - 127;
            float s = __int_as_float((127 - ebits) << 23);
            #pragma unroll
            for (int e = 0; e < 9; e++) dst[tid * 9 + e] = c[e] * s;
            lsd[tid] = lss[2 * tid] + lss[2 * tid + 1] + (float)ebits * LN2F;
        }
        __syncthreads();
        float* tmp = src; src = dst; dst = tmp;
        float* tl = lss; lss = lsd; lsd = tl;
        n = half;
    }

    if (tid == 0) {
        // row 0 of root = a_T (up to scale); logZ = ls + log(sum_j P[0][j]*e^stop_j)
        float z = src[0] * __expf(sp[0]) + src[1] * __expf(sp[1]) + src[2] * __expf(sp[2]);
        float logz = lss[0] + __logf(z);
        g_part[b] = seq_score - logz;
    }
    #undef TAG
}

// -------------------- kernel 3: mean-reduce 128 partials --------------------
__global__ void finalize_kernel(float* loss_out) {
    __shared__ float red[B_SZ];
    int tid = threadIdx.x;
    red[tid] = g_part[tid];
    __syncthreads();
    for (int h = B_SZ / 2; h; h >>= 1) {
        if (tid < h) red[tid] += red[tid + h];
        __syncthreads();
    }
    if (tid == 0) *loss_out = -red[0] / (float)B_SZ;
}

// -------------------- launch --------------------
extern "C" void kernel_launch(void* const* d_in, const int* in_sizes, int n_in,
                              void* d_out, int out_size)
{
    const float* x     = (const float*)d_in[0];
    const void*  y     = d_in[1];
    const float* W     = (const float*)d_in[2];
    const float* bias  = (const float*)d_in[3];
    const float* trans = (const float*)d_in[4];
    const float* st    = (const float*)d_in[5];
    const float* sp    = (const float*)d_in[6];
    float* out = (float*)d_out;

    int nrows = in_sizes[0] / H_DIM;                       // 65536
    int rows_per_warp = RQ * QUADS_PER_WARP;               // 8
    int warps = (nrows + rows_per_warp - 1) / rows_per_warp;
    int blocks = (warps * 32 + 255) / 256;                 // 1024

    pred_kernel<<<blocks, 256>>>(x, W, bias, out, nrows);
    crf_kernel<<<B_SZ, 256>>>(out, y, trans, st, sp);
    finalize_kernel<<<1, B_SZ>>>(out + (out_size - 1));
}